// round 5
// baseline (speedup 1.0000x reference)
#include <cuda_runtime.h>
#include <cstdint>

// AttentionConvolution2D: B=2, DIN=128, H=W=256, BS=4, NH=8, DH=32, DOUT=128
typedef unsigned long long u64;

__device__ __forceinline__ u64 as2(float lo, float hi) {
    u64 r; asm("mov.b64 %0, {%1,%2};" : "=l"(r) : "f"(lo), "f"(hi)); return r;
}
__device__ __forceinline__ float2 un2(u64 v) {
    float2 r; asm("mov.b64 {%0,%1}, %2;" : "=f"(r.x), "=f"(r.y) : "l"(v)); return r;
}
__device__ __forceinline__ u64 ffma2(u64 a, u64 b, u64 c) {
    u64 d; asm("fma.rn.f32x2 %0, %1, %2, %3;" : "=l"(d) : "l"(a), "l"(b), "l"(c)); return d;
}
__device__ __forceinline__ u64 fmul2(u64 a, u64 b) {
    u64 d; asm("mul.rn.f32x2 %0, %1, %2;" : "=l"(d) : "l"(a), "l"(b)); return d;
}
__device__ __forceinline__ u64 fadd2(u64 a, u64 b) {
    u64 d; asm("add.rn.f32x2 %0, %1, %2;" : "=l"(d) : "l"(a), "l"(b)); return d;
}
__device__ __forceinline__ void cpa16(uint32_t dst, const void* src) {
    asm volatile("cp.async.cg.shared.global [%0], [%1], 16;" :: "r"(dst), "l"(src));
}
__device__ __forceinline__ void cp_commit() {
    asm volatile("cp.async.commit_group;");
}
template <int N> __device__ __forceinline__ void cp_wait() {
    asm volatile("cp.async.wait_group %0;" :: "n"(N));
}

// proj scratch, tile-major: tile=(b*64+hb)*64+vb, row=pixel pi=(w&3)*4+(h&3),
// 768 ch/row ([0,256)=q, [256,512)=k, [512,768)=v)
__device__ float g_proj[100663296];   // 131072*768 floats
__device__ float g_wT[98304];         // w_in^T : [k=128][n=768]

// ---------------- K1: transpose w_in (768x128) -> g_wT (128x768) -------------
__global__ void winT_kernel(const float* __restrict__ w_in) {
    int idx = blockIdx.x * 256 + threadIdx.x;
    if (idx < 98304) {
        int n = idx >> 7, k = idx & 127;
        g_wT[k * 768 + n] = w_in[idx];
    }
}

// ---------------- K2: projection GEMM (64 px x 256 out x K=128) --------------
// 4 K-stages of 32, cp.async double-buffered. Stage = sA[32][64] + sB[32][256]
// = 40KB; two stages = 80KB dynamic smem. Thread tile: 4 px x 16 out.
#define PJ_STAGE 10240   // floats per stage

__global__ __launch_bounds__(256, 2) void proj_kernel(const float* __restrict__ x,
                                                      const float* __restrict__ b_in) {
    extern __shared__ float sm[];

    const int t   = threadIdx.x;
    const int nbk = blockIdx.x;           // 0..2
    const int pbk = blockIdx.y;           // 0..2047
    const int b   = pbk >> 10;
    const int rem = pbk & 1023;
    const int hc  = rem >> 2;             // h 0..255
    const int w0  = (rem & 3) << 6;       // first w of strip
    const int n0  = nbk << 8;             // 256 outputs per block

    const float* xb = x + ((size_t)b << 23) + (size_t)hc * 256 + w0;
    const int ti = t & 15, tj = t >> 4;

    const uint32_t smaddr = (uint32_t)__cvta_generic_to_shared(sm);

    // fill stage s (K rows s*32..) into parity p
    auto fill = [&](int s, int p) {
        const int ks = s << 5;
        uint32_t base = smaddr + p * (PJ_STAGE * 4);
#pragma unroll
        for (int r = 0; r < 2; ++r) {                 // sA: 2048 floats
            int flat = r * 1024 + t * 4;
            int k = flat >> 6, i = flat & 63;
            cpa16(base + flat * 4, xb + (size_t)(ks + k) * 65536 + i);
        }
#pragma unroll
        for (int r = 0; r < 8; ++r) {                 // sB: 8192 floats
            int flat = r * 1024 + t * 4;
            int k = flat >> 8, n = flat & 255;
            cpa16(base + 8192 + flat * 4, &g_wT[(ks + k) * 768 + n0 + n]);
        }
        cp_commit();
    };

    u64 acc[4][8];
#pragma unroll
    for (int i = 0; i < 4; ++i)
#pragma unroll
        for (int j = 0; j < 8; ++j) acc[i][j] = 0ull;

    auto compute = [&](int p) {
        const float* SA = sm + p * PJ_STAGE;
        const float* SB = SA + 2048;
        const float* pa = &SA[ti * 4];
        const u64*   pb = (const u64*)&SB[tj * 16];
#pragma unroll 4
        for (int k = 0; k < 32; ++k) {
            float4 a4 = *(const float4*)&pa[k * 64];
            u64 b0 = pb[k * 128 + 0], b1 = pb[k * 128 + 1];
            u64 b2 = pb[k * 128 + 2], b3 = pb[k * 128 + 3];
            u64 b4 = pb[k * 128 + 4], b5 = pb[k * 128 + 5];
            u64 b6 = pb[k * 128 + 6], b7 = pb[k * 128 + 7];
            u64 a0 = as2(a4.x, a4.x), a1 = as2(a4.y, a4.y);
            u64 a2 = as2(a4.z, a4.z), a3 = as2(a4.w, a4.w);
            acc[0][0] = ffma2(a0, b0, acc[0][0]); acc[0][1] = ffma2(a0, b1, acc[0][1]);
            acc[0][2] = ffma2(a0, b2, acc[0][2]); acc[0][3] = ffma2(a0, b3, acc[0][3]);
            acc[0][4] = ffma2(a0, b4, acc[0][4]); acc[0][5] = ffma2(a0, b5, acc[0][5]);
            acc[0][6] = ffma2(a0, b6, acc[0][6]); acc[0][7] = ffma2(a0, b7, acc[0][7]);
            acc[1][0] = ffma2(a1, b0, acc[1][0]); acc[1][1] = ffma2(a1, b1, acc[1][1]);
            acc[1][2] = ffma2(a1, b2, acc[1][2]); acc[1][3] = ffma2(a1, b3, acc[1][3]);
            acc[1][4] = ffma2(a1, b4, acc[1][4]); acc[1][5] = ffma2(a1, b5, acc[1][5]);
            acc[1][6] = ffma2(a1, b6, acc[1][6]); acc[1][7] = ffma2(a1, b7, acc[1][7]);
            acc[2][0] = ffma2(a2, b0, acc[2][0]); acc[2][1] = ffma2(a2, b1, acc[2][1]);
            acc[2][2] = ffma2(a2, b2, acc[2][2]); acc[2][3] = ffma2(a2, b3, acc[2][3]);
            acc[2][4] = ffma2(a2, b4, acc[2][4]); acc[2][5] = ffma2(a2, b5, acc[2][5]);
            acc[2][6] = ffma2(a2, b6, acc[2][6]); acc[2][7] = ffma2(a2, b7, acc[2][7]);
            acc[3][0] = ffma2(a3, b0, acc[3][0]); acc[3][1] = ffma2(a3, b1, acc[3][1]);
            acc[3][2] = ffma2(a3, b2, acc[3][2]); acc[3][3] = ffma2(a3, b3, acc[3][3]);
            acc[3][4] = ffma2(a3, b4, acc[3][4]); acc[3][5] = ffma2(a3, b5, acc[3][5]);
            acc[3][6] = ffma2(a3, b6, acc[3][6]); acc[3][7] = ffma2(a3, b7, acc[3][7]);
        }
    };

    fill(0, 0);
    fill(1, 1);
    cp_wait<1>(); __syncthreads();
    compute(0);  __syncthreads();
    fill(2, 0);
    cp_wait<1>(); __syncthreads();
    compute(1);  __syncthreads();
    fill(3, 1);
    cp_wait<1>(); __syncthreads();
    compute(0);  __syncthreads();
    cp_wait<0>(); __syncthreads();
    compute(1);

    // + bias, scatter to tile-major proj layout
    u64 bb[8];
    const u64* bi = (const u64*)&b_in[n0 + tj * 16];
#pragma unroll
    for (int j = 0; j < 8; ++j) bb[j] = bi[j];
    const int vb = hc >> 2, py = hc & 3;
#pragma unroll
    for (int i = 0; i < 4; ++i) {
        int w  = w0 + ti * 4 + i;
        int hb = w >> 2, px = w & 3;
        size_t base = ((((size_t)b * 64 + hb) * 64 + vb) * 16 + px * 4 + py) * 768 + n0 + tj * 16;
#pragma unroll
        for (int j = 0; j < 8; ++j)
            *(u64*)&g_proj[base + 2 * j] = fadd2(acc[i][j], bb[j]);
    }
}

// ---------------- K3: per-tile attention + fused output projection ----------
// smem (dynamic 80KB floats): sK0[4096] sK1[4096] sV0[4096] sV1[4096] sQO[4096]
// cp.async 2-deep pipeline over the valid-neighbor list.
__global__ __launch_bounds__(128) void attn_kernel(const float* __restrict__ pce,
                                                   const float* __restrict__ w_out,
                                                   const float* __restrict__ b_out,
                                                   float* __restrict__ out) {
    extern __shared__ float asm_[];
    float* sK[2] = { asm_,         asm_ + 4096 };
    float* sV[2] = { asm_ + 8192,  asm_ + 12288 };
    float* sQO   = asm_ + 16384;

    const int bid = blockIdx.x;
    const int vb = bid & 63;
    const int hb = (bid >> 6) & 63;
    const int b  = bid >> 12;
    const int t  = threadIdx.x;
    const int h  = t >> 4;        // head
    const int qi = t & 15;        // query pixel  (qi = px*4+py)
    const int qx = qi >> 2, qy = qi & 3;

    const float* tb = g_proj + (size_t)bid * 12288;
    const float SCALE = 0.17677669529663687f;   // 1/sqrt(32)

    // valid neighbor list
    int nidx[9], ndxy[9], n = 0;
    for (int dx = 0; dx < 3; ++dx) {
        int nhb = hb + dx - 1;
        if ((unsigned)nhb >= 64u) continue;      // == -inf boundary mask
        for (int dy = 0; dy < 3; ++dy) {
            int nvb = vb + dy - 1;
            if ((unsigned)nvb >= 64u) continue;
            nidx[n] = (b << 12) + (nhb << 6) + nvb;
            ndxy[n] = (dx << 4) | dy;
            ++n;
        }
    }

    const uint32_t aK[2] = { (uint32_t)__cvta_generic_to_shared(sK[0]),
                             (uint32_t)__cvta_generic_to_shared(sK[1]) };
    const uint32_t aV[2] = { (uint32_t)__cvta_generic_to_shared(sV[0]),
                             (uint32_t)__cvta_generic_to_shared(sV[1]) };

    auto fill = [&](int i, int p) {
        const float* nb = g_proj + (size_t)nidx[i] * 12288 + 256;
#pragma unroll
        for (int r = 0; r < 8; ++r) {
            int flat = r * 512 + t * 4;
            int row = flat >> 8, ch = flat & 255;
            cpa16(aK[p] + flat * 4, nb + row * 768 + ch);
            cpa16(aV[p] + flat * 4, nb + row * 768 + 256 + ch);
        }
        cp_commit();
    };

    // q for this thread, pre-scaled, packed in d-pairs
    u64 qreg[16];
    {
        const float* qp = tb + qi * 768 + (h << 5);
        u64 sc = as2(SCALE, SCALE);
#pragma unroll
        for (int d4 = 0; d4 < 32; d4 += 4) {
            float4 v = *(const float4*)&qp[d4];
            qreg[(d4 >> 1) + 0] = fmul2(as2(v.x, v.y), sc);
            qreg[(d4 >> 1) + 1] = fmul2(as2(v.z, v.w), sc);
        }
    }

    u64 acc[16];
#pragma unroll
    for (int dp = 0; dp < 16; ++dp) acc[dp] = 0ull;
    float m = -1e30f, l = 0.0f;
    const float* pceh = pce + (h << 8);

    fill(0, 0);
    if (n > 1) fill(1, 1);

    for (int i = 0; i < n; ++i) {
        if (i + 2 <= n) cp_wait<1>(); else cp_wait<0>();
        __syncthreads();
        const int p = i & 1;

        // scores for this neighbor's 16 keys
        float s[16];
        const int dx = ndxy[i] >> 4, dy = ndxy[i] & 15;
        const int bbias = 16 * ((dx << 2) + 4 - qx) + (dy << 2) + 4 - qy;
#pragma unroll
        for (int j = 0; j < 16; ++j) {
            const u64* kj = (const u64*)&sK[p][(j << 8) + (h << 5)];
            u64 a0 = 0ull, a1 = 0ull;
#pragma unroll
            for (int dp = 0; dp < 16; dp += 2) {
                a0 = ffma2(qreg[dp + 0], kj[dp + 0], a0);
                a1 = ffma2(qreg[dp + 1], kj[dp + 1], a1);
            }
            float2 r0 = un2(a0), r1 = un2(a1);
            s[j] = (r0.x + r0.y) + (r1.x + r1.y)
                 - __ldg(&pceh[bbias + ((j >> 2) << 4) + (j & 3)]);
        }

        // online softmax
        float mloc = s[0];
#pragma unroll
        for (int j = 1; j < 16; ++j) mloc = fmaxf(mloc, s[j]);
        float mnew = fmaxf(m, mloc);
        float corr = __expf(m - mnew);
        m = mnew;
        l *= corr;
        u64 c2 = as2(corr, corr);
#pragma unroll
        for (int dp = 0; dp < 16; ++dp) acc[dp] = fmul2(acc[dp], c2);
        float ls = 0.0f;
#pragma unroll
        for (int j = 0; j < 16; ++j) { s[j] = __expf(s[j] - mnew); ls += s[j]; }
        l += ls;

        // P @ V
#pragma unroll
        for (int j = 0; j < 16; ++j) {
            u64 p2 = as2(s[j], s[j]);
            const u64* vj = (const u64*)&sV[p][(j << 8) + (h << 5)];
#pragma unroll
            for (int dp = 0; dp < 16; ++dp)
                acc[dp] = ffma2(p2, vj[dp], acc[dp]);
        }

        __syncthreads();
        if (i + 2 < n) fill(i + 2, p);
    }

    // normalize, stash O (16 x 256) into sQO
    {
        float inv = 1.0f / l;
        u64 inv2 = as2(inv, inv);
#pragma unroll
        for (int dp = 0; dp < 16; ++dp)
            *(u64*)&sQO[qi * 256 + (h << 5) + dp * 2] = fmul2(acc[dp], inv2);
    }

    // fused output projection: out[qq][c] = sum_D O[qq][D]*w_out[c][D] + b_out
    const int cpair = t & 63, qg = t >> 6;
    const int lane = t & 31, wi = t >> 5;
    u64 accO[8];
#pragma unroll
    for (int q = 0; q < 8; ++q) accO[q] = 0ull;

    float* sW = sK[0];   // [d<32][c<128], row stride 130  (16.6KB, fits K bufs)
    for (int chunk = 0; chunk < 8; ++chunk) {
        int dc = chunk << 5;
        __syncthreads();
#pragma unroll
        for (int cc = wi; cc < 128; cc += 4)
            sW[lane * 130 + cc] = __ldg(&w_out[cc * 256 + dc + lane]);
        __syncthreads();
#pragma unroll
        for (int d4 = 0; d4 < 32; d4 += 4) {
            u64 w20 = *(const u64*)&sW[(d4 + 0) * 130 + cpair * 2];
            u64 w21 = *(const u64*)&sW[(d4 + 1) * 130 + cpair * 2];
            u64 w22 = *(const u64*)&sW[(d4 + 2) * 130 + cpair * 2];
            u64 w23 = *(const u64*)&sW[(d4 + 3) * 130 + cpair * 2];
#pragma unroll
            for (int q = 0; q < 8; ++q) {
                float4 o = *(const float4*)&sQO[(qg * 8 + q) * 256 + dc + d4];
                accO[q] = ffma2(as2(o.x, o.x), w20, accO[q]);
                accO[q] = ffma2(as2(o.y, o.y), w21, accO[q]);
                accO[q] = ffma2(as2(o.z, o.z), w22, accO[q]);
                accO[q] = ffma2(as2(o.w, o.w), w23, accO[q]);
            }
        }
    }

    // + b_out, store: out[b][c][h=vb*4+py][w=hb*4+px]
    const int c0 = cpair * 2;
    u64 bb = *(const u64*)&b_out[c0];
    size_t obase = ((size_t)b << 23) + (size_t)c0 * 65536 + (size_t)(vb * 4) * 256 + hb * 4;
#pragma unroll
    for (int q = 0; q < 8; ++q) {
        int qq = (qg << 3) + q;
        int px = qq >> 2, py = qq & 3;
        float2 r = un2(fadd2(accO[q], bb));
        size_t o = obase + (size_t)py * 256 + px;
        out[o]         = r.x;
        out[o + 65536] = r.y;
    }
}

// ---------------------------------------------------------------------------
extern "C" void kernel_launch(void* const* d_in, const int* in_sizes, int n_in,
                              void* d_out, int out_size) {
    (void)in_sizes; (void)n_in; (void)out_size;
    const float* x     = (const float*)d_in[0];
    const float* w_in  = (const float*)d_in[1];
    const float* b_in  = (const float*)d_in[2];
    const float* w_out = (const float*)d_in[3];
    const float* b_out = (const float*)d_in[4];
    const float* pce   = (const float*)d_in[5];
    float* out = (float*)d_out;

    static int configured = 0;
    if (!configured) {
        cudaFuncSetAttribute(proj_kernel, cudaFuncAttributeMaxDynamicSharedMemorySize, 81920);
        cudaFuncSetAttribute(attn_kernel, cudaFuncAttributeMaxDynamicSharedMemorySize, 81920);
        configured = 1;
    }

    winT_kernel<<<384, 256>>>(w_in);
    dim3 g(3, 2048);
    proj_kernel<<<g, 256, 81920>>>(x, b_in);
    attn_kernel<<<8192, 128, 81920>>>(pce, w_out, b_out, out);
}

// round 6
// speedup vs baseline: 1.2083x; 1.2083x over previous
#include <cuda_runtime.h>
#include <cstdint>

// AttentionConvolution2D: B=2, DIN=128, H=W=256, BS=4, NH=8, DH=32, DOUT=128
typedef unsigned long long u64;

__device__ __forceinline__ u64 as2(float lo, float hi) {
    u64 r; asm("mov.b64 %0, {%1,%2};" : "=l"(r) : "f"(lo), "f"(hi)); return r;
}
__device__ __forceinline__ float2 un2(u64 v) {
    float2 r; asm("mov.b64 {%0,%1}, %2;" : "=f"(r.x), "=f"(r.y) : "l"(v)); return r;
}
__device__ __forceinline__ u64 ffma2(u64 a, u64 b, u64 c) {
    u64 d; asm("fma.rn.f32x2 %0, %1, %2, %3;" : "=l"(d) : "l"(a), "l"(b), "l"(c)); return d;
}
__device__ __forceinline__ u64 fmul2(u64 a, u64 b) {
    u64 d; asm("mul.rn.f32x2 %0, %1, %2;" : "=l"(d) : "l"(a), "l"(b)); return d;
}
__device__ __forceinline__ u64 fadd2(u64 a, u64 b) {
    u64 d; asm("add.rn.f32x2 %0, %1, %2;" : "=l"(d) : "l"(a), "l"(b)); return d;
}
// LDS.128 producing two u64 operands directly (no packing MOVs)
__device__ __forceinline__ void lds2(u64& a, u64& b, uint32_t addr) {
    asm("ld.shared.v2.u64 {%0, %1}, [%2];" : "=l"(a), "=l"(b) : "r"(addr));
}

// proj scratch, tile-major: tile=(b*64+hb)*64+vb, row=pixel pi=(w&3)*4+(h&3),
// 768 ch/row ([0,256)=q, [256,512)=k, [512,768)=v)
__device__ float g_proj[100663296];   // 131072*768 floats
__device__ float g_wT[98304];         // w_in^T : [k=128][n=768]

// ---------------- K1: transpose w_in (768x128) -> g_wT (128x768) -------------
__global__ void winT_kernel(const float* __restrict__ w_in) {
    int idx = blockIdx.x * 256 + threadIdx.x;
    if (idx < 98304) {
        int n = idx >> 7, k = idx & 127;
        g_wT[k * 768 + n] = w_in[idx];
    }
}

// ---------------- K2: projection GEMM  (64 px x 128 out x K=128) -------------
__global__ __launch_bounds__(256, 2) void proj_kernel(const float* __restrict__ x,
                                                      const float* __restrict__ b_in) {
    __shared__ float sA[64 * 64];    // [k<64][i<64]   16KB
    __shared__ float sB[64 * 128];   // [k<64][n<128]  32KB

    const int t   = threadIdx.x;
    const int nbk = blockIdx.x;           // 0..5
    const int pbk = blockIdx.y;           // 0..2047
    const int b   = pbk >> 10;
    const int rem = pbk & 1023;
    const int hc  = rem >> 2;             // h 0..255
    const int w0  = (rem & 3) << 6;       // first w of strip
    const int n0  = nbk << 7;

    const float* xb = x + ((size_t)b << 23) + (size_t)hc * 256 + w0;
    const int ti = t & 15, tj = t >> 4;

    u64 acc[4][4];
#pragma unroll
    for (int i = 0; i < 4; ++i)
#pragma unroll
        for (int j = 0; j < 4; ++j) acc[i][j] = 0ull;

    const uint32_t sBaddr = (uint32_t)__cvta_generic_to_shared(sB);

    for (int kh = 0; kh < 2; ++kh) {
        const float* xk = xb + (size_t)(kh << 6) * 65536;
#pragma unroll
        for (int r = 0; r < 4; ++r) {                 // sA: 4096 floats
            int flat = r * 1024 + t * 4;
            int k = flat >> 6, i = flat & 63;
            *(float4*)&sA[flat] = *(const float4*)&xk[(size_t)k * 65536 + i];
        }
#pragma unroll
        for (int r = 0; r < 8; ++r) {                 // sB: 8192 floats
            int flat = r * 1024 + t * 4;
            int k = flat >> 7, n = flat & 127;
            *(float4*)&sB[flat] = *(const float4*)&g_wT[(kh * 64 + k) * 768 + n0 + n];
        }
        __syncthreads();

        const float* pa = &sA[ti * 4];
        const uint32_t pb = sBaddr + tj * 8 * 4;
#pragma unroll 4
        for (int k = 0; k < 64; ++k) {
            float4 a4 = *(const float4*)&pa[k * 64];
            u64 b0, b1, b2, b3;
            lds2(b0, b1, pb + k * 512);
            lds2(b2, b3, pb + k * 512 + 16);
            u64 a0 = as2(a4.x, a4.x), a1 = as2(a4.y, a4.y);
            u64 a2 = as2(a4.z, a4.z), a3 = as2(a4.w, a4.w);
            acc[0][0] = ffma2(a0, b0, acc[0][0]);
            acc[0][1] = ffma2(a0, b1, acc[0][1]);
            acc[0][2] = ffma2(a0, b2, acc[0][2]);
            acc[0][3] = ffma2(a0, b3, acc[0][3]);
            acc[1][0] = ffma2(a1, b0, acc[1][0]);
            acc[1][1] = ffma2(a1, b1, acc[1][1]);
            acc[1][2] = ffma2(a1, b2, acc[1][2]);
            acc[1][3] = ffma2(a1, b3, acc[1][3]);
            acc[2][0] = ffma2(a2, b0, acc[2][0]);
            acc[2][1] = ffma2(a2, b1, acc[2][1]);
            acc[2][2] = ffma2(a2, b2, acc[2][2]);
            acc[2][3] = ffma2(a2, b3, acc[2][3]);
            acc[3][0] = ffma2(a3, b0, acc[3][0]);
            acc[3][1] = ffma2(a3, b1, acc[3][1]);
            acc[3][2] = ffma2(a3, b2, acc[3][2]);
            acc[3][3] = ffma2(a3, b3, acc[3][3]);
        }
        __syncthreads();
    }

    // + bias, scatter to tile-major proj layout
    const u64* bi = (const u64*)&b_in[n0 + tj * 8];
    u64 bb0 = bi[0], bb1 = bi[1], bb2 = bi[2], bb3 = bi[3];
    const int vb = hc >> 2, py = hc & 3;
#pragma unroll
    for (int i = 0; i < 4; ++i) {
        int w  = w0 + ti * 4 + i;
        int hb = w >> 2, px = w & 3;
        size_t base = ((((size_t)b * 64 + hb) * 64 + vb) * 16 + px * 4 + py) * 768 + n0 + tj * 8;
        *(u64*)&g_proj[base + 0] = fadd2(acc[i][0], bb0);
        *(u64*)&g_proj[base + 2] = fadd2(acc[i][1], bb1);
        *(u64*)&g_proj[base + 4] = fadd2(acc[i][2], bb2);
        *(u64*)&g_proj[base + 6] = fadd2(acc[i][3], bb3);
    }
}

// ---------------- K3: per-tile attention + fused output projection ----------
__global__ __launch_bounds__(128, 4) void attn_kernel(const float* __restrict__ pce,
                                                      const float* __restrict__ w_out,
                                                      const float* __restrict__ b_out,
                                                      float* __restrict__ out) {
    __shared__ float sQO[4096];   // O stash (epilogue)     16KB
    __shared__ float sKV[8192];   // k|v of one neighbor    32KB (reused as sW)

    const int bid = blockIdx.x;
    const int vb = bid & 63;
    const int hb = (bid >> 6) & 63;
    const int b  = bid >> 12;
    const int t  = threadIdx.x;
    const int h  = t >> 4;        // head
    const int qi = t & 15;        // query pixel  (qi = px*4+py)
    const int qx = qi >> 2, qy = qi & 3;

    const float* tb = g_proj + (size_t)bid * 12288;
    const float SCALE = 0.17677669529663687f;   // 1/sqrt(32)
    const uint32_t skv = (uint32_t)__cvta_generic_to_shared(sKV);

    // q for this thread, pre-scaled, packed in d-pairs
    u64 qreg[16];
    {
        const float* qp = tb + qi * 768 + (h << 5);
        u64 sc = as2(SCALE, SCALE);
#pragma unroll
        for (int d4 = 0; d4 < 32; d4 += 4) {
            float4 v = *(const float4*)&qp[d4];
            qreg[(d4 >> 1) + 0] = fmul2(as2(v.x, v.y), sc);
            qreg[(d4 >> 1) + 1] = fmul2(as2(v.z, v.w), sc);
        }
    }

    u64 acc[16];
#pragma unroll
    for (int dp = 0; dp < 16; ++dp) acc[dp] = 0ull;
    float m = -1e30f, l = 0.0f;
    const float* pceh = pce + (h << 8);

    for (int dx = 0; dx < 3; ++dx) {
        int nhb = hb + dx - 1;
        if ((unsigned)nhb >= 64u) continue;          // == -inf boundary mask
        for (int dy = 0; dy < 3; ++dy) {
            int nvb = vb + dy - 1;
            if ((unsigned)nvb >= 64u) continue;

            __syncthreads();                          // prev KV consumed
            const float* nb = g_proj + (size_t)((b << 12) + (nhb << 6) + nvb) * 12288 + 256;
#pragma unroll
            for (int r = 0; r < 16; ++r) {
                int flat = r * 512 + t * 4;
                int row = flat >> 9, ch = flat & 511;
                *(float4*)&sKV[flat] = *(const float4*)&nb[row * 768 + ch];
            }
            __syncthreads();

            // scores for this neighbor's 16 keys
            float s[16];
            const int bbias = 16 * ((dx << 2) + 4 - qx) + (dy << 2) + 4 - qy;
#pragma unroll
            for (int j = 0; j < 16; ++j) {
                const uint32_t kaddr = skv + (((j << 9) + (h << 5)) << 2);
                u64 a0 = 0ull, a1 = 0ull;
#pragma unroll
                for (int dp = 0; dp < 16; dp += 4) {
                    u64 k0, k1, k2, k3;
                    lds2(k0, k1, kaddr + dp * 8);
                    lds2(k2, k3, kaddr + dp * 8 + 16);
                    a0 = ffma2(qreg[dp + 0], k0, a0);
                    a1 = ffma2(qreg[dp + 1], k1, a1);
                    a0 = ffma2(qreg[dp + 2], k2, a0);
                    a1 = ffma2(qreg[dp + 3], k3, a1);
                }
                float2 r0 = un2(a0), r1 = un2(a1);
                s[j] = (r0.x + r0.y) + (r1.x + r1.y)
                     - __ldg(&pceh[bbias + ((j >> 2) << 4) + (j & 3)]);
            }

            // online softmax
            float mloc = s[0];
#pragma unroll
            for (int j = 1; j < 16; ++j) mloc = fmaxf(mloc, s[j]);
            float mnew = fmaxf(m, mloc);
            float corr = __expf(m - mnew);
            m = mnew;
            l *= corr;
            u64 c2 = as2(corr, corr);
#pragma unroll
            for (int dp = 0; dp < 16; ++dp) acc[dp] = fmul2(acc[dp], c2);
            float ls = 0.0f;
#pragma unroll
            for (int j = 0; j < 16; ++j) { s[j] = __expf(s[j] - mnew); ls += s[j]; }
            l += ls;

            // P @ V
#pragma unroll
            for (int j = 0; j < 16; ++j) {
                u64 p2 = as2(s[j], s[j]);
                const uint32_t vaddr = skv + (((j << 9) + 256 + (h << 5)) << 2);
#pragma unroll
                for (int dp = 0; dp < 16; dp += 4) {
                    u64 v0, v1, v2, v3;
                    lds2(v0, v1, vaddr + dp * 8);
                    lds2(v2, v3, vaddr + dp * 8 + 16);
                    acc[dp + 0] = ffma2(p2, v0, acc[dp + 0]);
                    acc[dp + 1] = ffma2(p2, v1, acc[dp + 1]);
                    acc[dp + 2] = ffma2(p2, v2, acc[dp + 2]);
                    acc[dp + 3] = ffma2(p2, v3, acc[dp + 3]);
                }
            }
        }
    }

    // normalize, stash O (16 x 256) into sQO
    {
        float inv = 1.0f / l;
        u64 inv2 = as2(inv, inv);
#pragma unroll
        for (int dp = 0; dp < 16; ++dp)
            *(u64*)&sQO[qi * 256 + (h << 5) + dp * 2] = fmul2(acc[dp], inv2);
    }
    __syncthreads();

    // fused output projection: out[qq][c] = sum_D O[qq][D]*w_out[c][D] + b_out
    const int cpair = t & 63, qg = t >> 6;
    const int lane = t & 31, wi = t >> 5;
    u64 accO[8];
#pragma unroll
    for (int q = 0; q < 8; ++q) accO[q] = 0ull;

    float* sW = sKV;   // [d<32][c<128], row stride 130
    for (int chunk = 0; chunk < 8; ++chunk) {
        int dc = chunk << 5;
        __syncthreads();
#pragma unroll
        for (int cc = wi; cc < 128; cc += 4)
            sW[lane * 130 + cc] = __ldg(&w_out[cc * 256 + dc + lane]);
        __syncthreads();
#pragma unroll
        for (int d4 = 0; d4 < 32; d4 += 4) {
            u64 w20 = *(const u64*)&sW[(d4 + 0) * 130 + cpair * 2];
            u64 w21 = *(const u64*)&sW[(d4 + 1) * 130 + cpair * 2];
            u64 w22 = *(const u64*)&sW[(d4 + 2) * 130 + cpair * 2];
            u64 w23 = *(const u64*)&sW[(d4 + 3) * 130 + cpair * 2];
#pragma unroll
            for (int q = 0; q < 8; ++q) {
                float4 o = *(const float4*)&sQO[(qg * 8 + q) * 256 + dc + d4];
                accO[q] = ffma2(as2(o.x, o.x), w20, accO[q]);
                accO[q] = ffma2(as2(o.y, o.y), w21, accO[q]);
                accO[q] = ffma2(as2(o.z, o.z), w22, accO[q]);
                accO[q] = ffma2(as2(o.w, o.w), w23, accO[q]);
            }
        }
    }

    // + b_out, store: out[b][c][h=vb*4+py][w=hb*4+px]
    const int c0 = cpair * 2;
    u64 bb = *(const u64*)&b_out[c0];
    size_t obase = ((size_t)b << 23) + (size_t)c0 * 65536 + (size_t)(vb * 4) * 256 + hb * 4;
#pragma unroll
    for (int q = 0; q < 8; ++q) {
        int qq = (qg << 3) + q;
        int px = qq >> 2, py = qq & 3;
        float2 r = un2(fadd2(accO[q], bb));
        size_t o = obase + (size_t)py * 256 + px;
        out[o]         = r.x;
        out[o + 65536] = r.y;
    }
}

// ---------------------------------------------------------------------------
extern "C" void kernel_launch(void* const* d_in, const int* in_sizes, int n_in,
                              void* d_out, int out_size) {
    (void)in_sizes; (void)n_in; (void)out_size;
    const float* x     = (const float*)d_in[0];
    const float* w_in  = (const float*)d_in[1];
    const float* b_in  = (const float*)d_in[2];
    const float* w_out = (const float*)d_in[3];
    const float* b_out = (const float*)d_in[4];
    const float* pce   = (const float*)d_in[5];
    float* out = (float*)d_out;

    winT_kernel<<<384, 256>>>(w_in);
    dim3 g(6, 2048);
    proj_kernel<<<g, 256>>>(x, b_in);
    attn_kernel<<<8192, 128>>>(pce, w_out, b_out, out);
}